// round 12
// baseline (speedup 1.0000x reference)
#include <cuda_runtime.h>

#define VOCAB 50000
#define EMB   512
#define HID   1024
#define OUTD  4
#define BATCH 128
#define TLEN  256

// Scratch (allocation-free rule: __device__ globals)
__device__ float g_X0[(size_t)TLEN * BATCH * HID];   // precomputed x2h0(x_t)+b0, [t][b][j]
__device__ float g_h0[2][BATCH * HID];               // ping-pong layer-0 hidden
__device__ float g_h1[2][BATCH * HID];               // ping-pong layer-1 hidden
__device__ float g_acc1[BATCH * HID];                // h1 @ h2h_w1^T partial for current step

// Accurate tanh immune to --use_fast_math's tanh.approx lowering.
// __expf is MUFU.EX2-based, ~2 ulp; abs error of result ~2e-6.
__device__ __forceinline__ float tanh_acc(float x) {
    float t = __expf(-2.0f * fabsf(x));
    float r = (1.0f - t) / (1.0f + t);
    return copysignf(r, x);
}

__global__ void init_kernel() {
    int i = blockIdx.x * blockDim.x + threadIdx.x;
    if (i < BATCH * HID) { g_h0[0][i] = 0.0f; g_h1[0][i] = 0.0f; }
}

// ---------------------------------------------------------------------------
// Precompute X0[r][n] = sum_k emb[fx[r]][k] * w0[n][k] + b0[n],
// r = t*128 + b (row-gathered GEMM, M=32768, N=1024, K=512).
// BM=64, BN=64, BK=32, 256 threads, 4x4 microtile.
// ---------------------------------------------------------------------------
__global__ __launch_bounds__(256) void embed_gemm_kernel(
    const int* __restrict__ fx, const float* __restrict__ emb,
    const float* __restrict__ w0, const float* __restrict__ b0)
{
    __shared__ float As[32][65];   // [k][m], pad 1 -> conflict-free scalar access
    __shared__ float Bs[32][65];   // [k][n]
    __shared__ int rowfx[64];

    const int tid = threadIdx.x;
    const int m0 = blockIdx.y * 64;      // global row block, [0, 32768)
    const int n0 = blockIdx.x * 64;      // HID col block

    if (tid < 64) {
        int r = m0 + tid;
        int t = r >> 7;                  // r / 128
        int b = r & 127;
        rowfx[tid] = fx[b * TLEN + t];
    }
    __syncthreads();

    const int ar = tid >> 3;             // 0..31
    const int lk = (tid & 7) << 2;       // 0,4,...,28

    const float* Ap0 = emb + (size_t)rowfx[ar] * EMB + lk;
    const float* Ap1 = emb + (size_t)rowfx[ar + 32] * EMB + lk;
    const float* Bp0 = w0 + (size_t)(n0 + ar) * EMB + lk;
    const float* Bp1 = w0 + (size_t)(n0 + ar + 32) * EMB + lk;

    float4 pa0 = *(const float4*)Ap0;
    float4 pa1 = *(const float4*)Ap1;
    float4 pb0 = *(const float4*)Bp0;
    float4 pb1 = *(const float4*)Bp1;

    const int tm = tid >> 4;             // 0..15
    const int tn = tid & 15;             // 0..15
    float acc[4][4] = {};

    const int NT = EMB / 32;             // 16
    for (int kt = 0; kt < NT; kt++) {
        As[lk+0][ar]    = pa0.x; As[lk+1][ar]    = pa0.y; As[lk+2][ar]    = pa0.z; As[lk+3][ar]    = pa0.w;
        As[lk+0][ar+32] = pa1.x; As[lk+1][ar+32] = pa1.y; As[lk+2][ar+32] = pa1.z; As[lk+3][ar+32] = pa1.w;
        Bs[lk+0][ar]    = pb0.x; Bs[lk+1][ar]    = pb0.y; Bs[lk+2][ar]    = pb0.z; Bs[lk+3][ar]    = pb0.w;
        Bs[lk+0][ar+32] = pb1.x; Bs[lk+1][ar+32] = pb1.y; Bs[lk+2][ar+32] = pb1.z; Bs[lk+3][ar+32] = pb1.w;
        __syncthreads();
        if (kt + 1 < NT) {
            int ko = (kt + 1) * 32;
            pa0 = *(const float4*)(Ap0 + ko);
            pa1 = *(const float4*)(Ap1 + ko);
            pb0 = *(const float4*)(Bp0 + ko);
            pb1 = *(const float4*)(Bp1 + ko);
        }
        #pragma unroll
        for (int kk = 0; kk < 32; kk++) {
            float a0 = As[kk][(tm<<2)+0], a1 = As[kk][(tm<<2)+1];
            float a2 = As[kk][(tm<<2)+2], a3 = As[kk][(tm<<2)+3];
            float c0 = Bs[kk][(tn<<2)+0], c1 = Bs[kk][(tn<<2)+1];
            float c2 = Bs[kk][(tn<<2)+2], c3 = Bs[kk][(tn<<2)+3];
            acc[0][0] = fmaf(a0,c0,acc[0][0]); acc[0][1] = fmaf(a0,c1,acc[0][1]);
            acc[0][2] = fmaf(a0,c2,acc[0][2]); acc[0][3] = fmaf(a0,c3,acc[0][3]);
            acc[1][0] = fmaf(a1,c0,acc[1][0]); acc[1][1] = fmaf(a1,c1,acc[1][1]);
            acc[1][2] = fmaf(a1,c2,acc[1][2]); acc[1][3] = fmaf(a1,c3,acc[1][3]);
            acc[2][0] = fmaf(a2,c0,acc[2][0]); acc[2][1] = fmaf(a2,c1,acc[2][1]);
            acc[2][2] = fmaf(a2,c2,acc[2][2]); acc[2][3] = fmaf(a2,c3,acc[2][3]);
            acc[3][0] = fmaf(a3,c0,acc[3][0]); acc[3][1] = fmaf(a3,c1,acc[3][1]);
            acc[3][2] = fmaf(a3,c2,acc[3][2]); acc[3][3] = fmaf(a3,c3,acc[3][3]);
        }
        __syncthreads();
    }

    #pragma unroll
    for (int i = 0; i < 4; i++) {
        int r = m0 + (tm << 2) + i;
        #pragma unroll
        for (int j = 0; j < 4; j++) {
            int n = n0 + (tn << 2) + j;
            g_X0[(size_t)r * HID + n] = acc[i][j] + b0[n];
        }
    }
}

// ---------------------------------------------------------------------------
// Phase A (per step): z=0: h0' = tanh(X0[t] + h0 @ Wh0^T + bh0)
//                     z=1: acc1 = h1 @ Wh1^T
// M=128, N=1024, K=1024. BM=32, BN=64, BK=32, 128 threads, 4x4 microtile.
// Grid: (16, 4, 2) = 128 CTAs.
// ---------------------------------------------------------------------------
__global__ __launch_bounds__(128) void step_a_kernel(
    int t, int rd, int wr,
    const float* __restrict__ Wh0, const float* __restrict__ bh0,
    const float* __restrict__ Wh1)
{
    __shared__ float As[32][33];
    __shared__ float Bs[32][65];

    const int tid   = threadIdx.x;
    const int layer = blockIdx.z;
    const float* A  = layer ? g_h1[rd] : g_h0[rd];
    const float* W  = layer ? Wh1 : Wh0;
    const int m0 = blockIdx.y * 32;
    const int n0 = blockIdx.x * 64;

    const int ar = tid >> 3;             // 0..15
    const int lk = (tid & 7) << 2;

    const float* Ap = A + (size_t)(m0 + ar) * HID + lk;
    const float* Bp = W + (size_t)(n0 + ar) * HID + lk;

    float4 pa0 = *(const float4*)(Ap);
    float4 pa1 = *(const float4*)(Ap + 16 * HID);
    float4 pb0 = *(const float4*)(Bp);
    float4 pb1 = *(const float4*)(Bp + 16 * HID);
    float4 pb2 = *(const float4*)(Bp + 32 * HID);
    float4 pb3 = *(const float4*)(Bp + 48 * HID);

    const int tm = tid >> 4;             // 0..7
    const int tn = tid & 15;             // 0..15
    float acc[4][4] = {};

    const int NT = HID / 32;             // 32
    for (int kt = 0; kt < NT; kt++) {
        As[lk+0][ar]    = pa0.x; As[lk+1][ar]    = pa0.y; As[lk+2][ar]    = pa0.z; As[lk+3][ar]    = pa0.w;
        As[lk+0][ar+16] = pa1.x; As[lk+1][ar+16] = pa1.y; As[lk+2][ar+16] = pa1.z; As[lk+3][ar+16] = pa1.w;
        Bs[lk+0][ar]    = pb0.x; Bs[lk+1][ar]    = pb0.y; Bs[lk+2][ar]    = pb0.z; Bs[lk+3][ar]    = pb0.w;
        Bs[lk+0][ar+16] = pb1.x; Bs[lk+1][ar+16] = pb1.y; Bs[lk+2][ar+16] = pb1.z; Bs[lk+3][ar+16] = pb1.w;
        Bs[lk+0][ar+32] = pb2.x; Bs[lk+1][ar+32] = pb2.y; Bs[lk+2][ar+32] = pb2.z; Bs[lk+3][ar+32] = pb2.w;
        Bs[lk+0][ar+48] = pb3.x; Bs[lk+1][ar+48] = pb3.y; Bs[lk+2][ar+48] = pb3.z; Bs[lk+3][ar+48] = pb3.w;
        __syncthreads();
        if (kt + 1 < NT) {
            int ko = (kt + 1) * 32;
            pa0 = *(const float4*)(Ap + ko);
            pa1 = *(const float4*)(Ap + 16 * HID + ko);
            pb0 = *(const float4*)(Bp + ko);
            pb1 = *(const float4*)(Bp + 16 * HID + ko);
            pb2 = *(const float4*)(Bp + 32 * HID + ko);
            pb3 = *(const float4*)(Bp + 48 * HID + ko);
        }
        #pragma unroll
        for (int kk = 0; kk < 32; kk++) {
            float a0 = As[kk][(tm<<2)+0], a1 = As[kk][(tm<<2)+1];
            float a2 = As[kk][(tm<<2)+2], a3 = As[kk][(tm<<2)+3];
            float c0 = Bs[kk][(tn<<2)+0], c1 = Bs[kk][(tn<<2)+1];
            float c2 = Bs[kk][(tn<<2)+2], c3 = Bs[kk][(tn<<2)+3];
            acc[0][0] = fmaf(a0,c0,acc[0][0]); acc[0][1] = fmaf(a0,c1,acc[0][1]);
            acc[0][2] = fmaf(a0,c2,acc[0][2]); acc[0][3] = fmaf(a0,c3,acc[0][3]);
            acc[1][0] = fmaf(a1,c0,acc[1][0]); acc[1][1] = fmaf(a1,c1,acc[1][1]);
            acc[1][2] = fmaf(a1,c2,acc[1][2]); acc[1][3] = fmaf(a1,c3,acc[1][3]);
            acc[2][0] = fmaf(a2,c0,acc[2][0]); acc[2][1] = fmaf(a2,c1,acc[2][1]);
            acc[2][2] = fmaf(a2,c2,acc[2][2]); acc[2][3] = fmaf(a2,c3,acc[2][3]);
            acc[3][0] = fmaf(a3,c0,acc[3][0]); acc[3][1] = fmaf(a3,c1,acc[3][1]);
            acc[3][2] = fmaf(a3,c2,acc[3][2]); acc[3][3] = fmaf(a3,c3,acc[3][3]);
        }
        __syncthreads();
    }

    if (layer == 0) {
        const float* x0t = g_X0 + (size_t)t * (BATCH * HID);
        float* h0w = g_h0[wr];
        #pragma unroll
        for (int i = 0; i < 4; i++) {
            int m = m0 + (tm << 2) + i;
            #pragma unroll
            for (int j = 0; j < 4; j++) {
                int n   = n0 + (tn << 2) + j;
                int idx = m * HID + n;
                h0w[idx] = tanh_acc(acc[i][j] + x0t[idx] + bh0[n]);
            }
        }
    } else {
        #pragma unroll
        for (int i = 0; i < 4; i++) {
            int m = m0 + (tm << 2) + i;
            #pragma unroll
            for (int j = 0; j < 4; j++) {
                int n = n0 + (tn << 2) + j;
                g_acc1[m * HID + n] = acc[i][j];
            }
        }
    }
}

// ---------------------------------------------------------------------------
// Phase B (per step): h1' = tanh(h0' @ Wx1^T + acc1 + bx1 + bh1)
// M=128, N=1024, K=1024. BM=32, BN=32, BK=32, 128 threads, 4x2 microtile.
// Grid: (32, 4) = 128 CTAs.
// ---------------------------------------------------------------------------
__global__ __launch_bounds__(128) void step_b_kernel(
    int wr, const float* __restrict__ Wx1,
    const float* __restrict__ bx1, const float* __restrict__ bh1)
{
    __shared__ float As[32][33];
    __shared__ float Bs[32][33];

    const int tid = threadIdx.x;
    const float* A = g_h0[wr];           // freshly-written layer-0 hidden
    const int m0 = blockIdx.y * 32;
    const int n0 = blockIdx.x * 32;

    const int ar = tid >> 3;             // 0..15
    const int lk = (tid & 7) << 2;

    const float* Ap = A + (size_t)(m0 + ar) * HID + lk;
    const float* Bp = Wx1 + (size_t)(n0 + ar) * HID + lk;

    float4 pa0 = *(const float4*)(Ap);
    float4 pa1 = *(const float4*)(Ap + 16 * HID);
    float4 pb0 = *(const float4*)(Bp);
    float4 pb1 = *(const float4*)(Bp + 16 * HID);

    const int tm = tid >> 4;             // 0..7
    const int tn = tid & 15;             // 0..15
    float acc[4][2] = {};

    const int NT = HID / 32;             // 32
    for (int kt = 0; kt < NT; kt++) {
        As[lk+0][ar]    = pa0.x; As[lk+1][ar]    = pa0.y; As[lk+2][ar]    = pa0.z; As[lk+3][ar]    = pa0.w;
        As[lk+0][ar+16] = pa1.x; As[lk+1][ar+16] = pa1.y; As[lk+2][ar+16] = pa1.z; As[lk+3][ar+16] = pa1.w;
        Bs[lk+0][ar]    = pb0.x; Bs[lk+1][ar]    = pb0.y; Bs[lk+2][ar]    = pb0.z; Bs[lk+3][ar]    = pb0.w;
        Bs[lk+0][ar+16] = pb1.x; Bs[lk+1][ar+16] = pb1.y; Bs[lk+2][ar+16] = pb1.z; Bs[lk+3][ar+16] = pb1.w;
        __syncthreads();
        if (kt + 1 < NT) {
            int ko = (kt + 1) * 32;
            pa0 = *(const float4*)(Ap + ko);
            pa1 = *(const float4*)(Ap + 16 * HID + ko);
            pb0 = *(const float4*)(Bp + ko);
            pb1 = *(const float4*)(Bp + 16 * HID + ko);
        }
        #pragma unroll
        for (int kk = 0; kk < 32; kk++) {
            float a0 = As[kk][(tm<<2)+0], a1 = As[kk][(tm<<2)+1];
            float a2 = As[kk][(tm<<2)+2], a3 = As[kk][(tm<<2)+3];
            float c0 = Bs[kk][(tn<<1)+0], c1 = Bs[kk][(tn<<1)+1];
            acc[0][0] = fmaf(a0,c0,acc[0][0]); acc[0][1] = fmaf(a0,c1,acc[0][1]);
            acc[1][0] = fmaf(a1,c0,acc[1][0]); acc[1][1] = fmaf(a1,c1,acc[1][1]);
            acc[2][0] = fmaf(a2,c0,acc[2][0]); acc[2][1] = fmaf(a2,c1,acc[2][1]);
            acc[3][0] = fmaf(a3,c0,acc[3][0]); acc[3][1] = fmaf(a3,c1,acc[3][1]);
        }
        __syncthreads();
    }

    float* h1w = g_h1[wr];
    #pragma unroll
    for (int i = 0; i < 4; i++) {
        int m = m0 + (tm << 2) + i;
        #pragma unroll
        for (int j = 0; j < 2; j++) {
            int n   = n0 + (tn << 1) + j;
            int idx = m * HID + n;
            h1w[idx] = tanh_acc(acc[i][j] + g_acc1[idx] + bx1[n] + bh1[n]);
        }
    }
}

// ---------------------------------------------------------------------------
// Final projection: out[b][o] = h1[b] . fc_w[o] + fc_b[o]
// One block per batch row; fixed-order tree reduction (deterministic).
// ---------------------------------------------------------------------------
__global__ __launch_bounds__(128) void fc_kernel(
    const float* __restrict__ fcw, const float* __restrict__ fcb,
    float* __restrict__ out)
{
    const int b = blockIdx.x;
    const int tid = threadIdx.x;
    const float* h = g_h1[0] + b * HID;  // t=255: wr = (255&1)^1 = 0

    float a0 = 0.f, a1 = 0.f, a2 = 0.f, a3 = 0.f;
    for (int k = tid; k < HID; k += 128) {
        float hv = h[k];
        a0 = fmaf(hv, fcw[0 * HID + k], a0);
        a1 = fmaf(hv, fcw[1 * HID + k], a1);
        a2 = fmaf(hv, fcw[2 * HID + k], a2);
        a3 = fmaf(hv, fcw[3 * HID + k], a3);
    }
    __shared__ float red[4][128];
    red[0][tid] = a0; red[1][tid] = a1; red[2][tid] = a2; red[3][tid] = a3;
    __syncthreads();
    for (int s = 64; s > 0; s >>= 1) {
        if (tid < s) {
            #pragma unroll
            for (int o = 0; o < 4; o++) red[o][tid] += red[o][tid + s];
        }
        __syncthreads();
    }
    if (tid < 4) out[b * OUTD + tid] = red[tid][0] + fcb[tid];
}

// ---------------------------------------------------------------------------
extern "C" void kernel_launch(void* const* d_in, const int* in_sizes, int n_in,
                              void* d_out, int out_size) {
    (void)in_sizes; (void)n_in; (void)out_size;
    const int*   fx     = (const int*)  d_in[0];
    const float* emb    = (const float*)d_in[1];
    const float* x2h_w0 = (const float*)d_in[2];
    const float* x2h_b0 = (const float*)d_in[3];
    const float* h2h_w0 = (const float*)d_in[4];
    const float* h2h_b0 = (const float*)d_in[5];
    const float* x2h_w1 = (const float*)d_in[6];
    const float* x2h_b1 = (const float*)d_in[7];
    const float* h2h_w1 = (const float*)d_in[8];
    const float* h2h_b1 = (const float*)d_in[9];
    const float* fc_w   = (const float*)d_in[10];
    const float* fc_b   = (const float*)d_in[11];
    float* out = (float*)d_out;

    init_kernel<<<(BATCH * HID + 255) / 256, 256>>>();

    // X0[t][b][:] = x2h0(emb[fx[b][t]]) + b0  — off the sequential critical path
    embed_gemm_kernel<<<dim3(HID / 64, (BATCH * TLEN) / 64), 256>>>(fx, emb, x2h_w0, x2h_b0);

    for (int t = 0; t < TLEN; t++) {
        int rd = t & 1, wr = rd ^ 1;
        step_a_kernel<<<dim3(HID / 64, BATCH / 32, 2), 128>>>(t, rd, wr, h2h_w0, h2h_b0, h2h_w1);
        step_b_kernel<<<dim3(HID / 32, BATCH / 32), 128>>>(wr, x2h_w1, x2h_b1, h2h_b1);
    }

    fc_kernel<<<BATCH, 128>>>(fc_w, fc_b, out);
}